// round 10
// baseline (speedup 1.0000x reference)
#include <cuda_runtime.h>
#include <stdint.h>

#define L 2048
#define NT 256
#define PT 8
#define NW (NT / 32)
#define BMAX 4096

__device__ float g_row_loss[BMAX];
__device__ unsigned int g_counter = 0;

// Map float -> uint such that uint order == float ascending order.
__device__ __forceinline__ unsigned int f2u_ord(float f) {
    unsigned int u = __float_as_uint(f);
    return (u & 0x80000000u) ? ~u : (u | 0x80000000u);
}

// Bucket id (0..2047), an exact monotone-nondecreasing function of the key.
// Reconstruct canonical target from key's top 21 bits, map through a logistic
// CDF (targets ~ N(0,1)) so occupancy is ~Poisson(1).
__device__ __forceinline__ unsigned int bucket_of(unsigned int key) {
    const unsigned int o = (~key) & 0xFFFFF800u;       // truncated ord(t)
    const unsigned int u = (o & 0x80000000u) ? (o ^ 0x80000000u) : ~o;
    const float t = __uint_as_float(u);
    const float p = __fdividef(2048.0f, 1.0f + __expf(1.702f * t));
    int b = (int)p;                                     // decreasing in t
    return (unsigned int)min(b, 2047);
}

__global__ __launch_bounds__(NT)
void listmle_fused_kernel(const float* __restrict__ preds,
                          const float* __restrict__ targs,
                          float* __restrict__ out) {
    __shared__ float spred[L];              // 8 KB  preds by original index
    __shared__ unsigned int hist[L];        // 8 KB  counts -> exclusive base
    __shared__ unsigned int skeys[L];       // 8 KB  keys, then sorted preds
    __shared__ unsigned int uwarp[NW];
    __shared__ float swarp[NW];
    __shared__ unsigned int isLast;

    const int row  = blockIdx.x;
    const int B    = gridDim.x;
    const int tid  = threadIdx.x;
    const int lane = tid & 31;
    const int warp = tid >> 5;

    const float4* p4 = (const float4*)(preds + (size_t)row * L);
    const float4* t4 = (const float4*)(targs + (size_t)row * L);

    // ---- phase 0: stage preds; build keys + buckets; zero hist ----
    // key = top-21 bits of ~ord(target) | 11-bit original index (all distinct)
    unsigned int k[PT], bkt[PT];
    #pragma unroll
    for (int u = 0; u < 2; u++) {
        ((float4*)spred)[u * NT + tid] = p4[u * NT + tid];
        const float4 tv = t4[u * NT + tid];
        const unsigned int e = (unsigned int)((u * NT + tid) * 4);
        k[4*u+0] = (~f2u_ord(tv.x) & 0xFFFFF800u) | (e + 0u);
        k[4*u+1] = (~f2u_ord(tv.y) & 0xFFFFF800u) | (e + 1u);
        k[4*u+2] = (~f2u_ord(tv.z) & 0xFFFFF800u) | (e + 2u);
        k[4*u+3] = (~f2u_ord(tv.w) & 0xFFFFF800u) | (e + 3u);
    }
    #pragma unroll
    for (int c = 0; c < PT; c++) bkt[c] = bucket_of(k[c]);
    ((uint4*)hist)[tid]      = make_uint4(0u, 0u, 0u, 0u);
    ((uint4*)hist)[NT + tid] = make_uint4(0u, 0u, 0u, 0u);
    __syncthreads();

    // ---- phase 1: histogram, remember arrival index ----
    unsigned int arr[PT];
    #pragma unroll
    for (int c = 0; c < PT; c++)
        arr[c] = atomicAdd(&hist[bkt[c]], 1u);
    __syncthreads();

    // ---- phase 2: exclusive scan of hist[2048] in place ----
    unsigned int h[PT];
    unsigned int tsum = 0u;
    #pragma unroll
    for (int c = 0; c < PT; c++) h[c] = hist[tid * PT + c];
    #pragma unroll
    for (int c = 0; c < PT; c++) { const unsigned int t = h[c]; h[c] = tsum; tsum += t; }
    unsigned int x = tsum;
    #pragma unroll
    for (int o = 1; o < 32; o <<= 1) {
        const unsigned int n = __shfl_up_sync(0xffffffffu, x, o);
        if (lane >= o) x += n;
    }
    if (lane == 31) uwarp[warp] = x;
    __syncthreads();
    if (warp == 0) {
        unsigned int w = (lane < NW) ? uwarp[lane] : 0u;
        #pragma unroll
        for (int o = 1; o < NW; o <<= 1) {
            const unsigned int n = __shfl_up_sync(0xffffffffu, w, o);
            if (lane >= o) w += n;
        }
        if (lane < NW) uwarp[lane] = w;
    }
    __syncthreads();
    const unsigned int excl = (x - tsum) + (warp > 0 ? uwarp[warp - 1] : 0u);
    #pragma unroll
    for (int c = 0; c < PT; c++) hist[tid * PT + c] = h[c] + excl;
    __syncthreads();

    // ---- phase 3: scatter keys into bucket-contiguous slots ----
    #pragma unroll
    for (int c = 0; c < PT; c++)
        skeys[hist[bkt[c]] + arr[c]] = k[c];
    __syncthreads();

    // ---- phase 4a: exact in-bucket rank (full-key compare) -> registers ----
    unsigned int pos[PT];
    #pragma unroll
    for (int c = 0; c < PT; c++) {
        const unsigned int key  = k[c];
        const unsigned int d    = bkt[c];
        const unsigned int b    = hist[d];
        const unsigned int bend = (d < 2047u) ? hist[d + 1] : (unsigned int)L;
        unsigned int r = 0u;
        for (unsigned int p = b; p < bend; p++)
            r += (skeys[p] < key) ? 1u : 0u;
        pos[c] = b + r;
    }
    __syncthreads();

    // ---- phase 4b: write sorted pred values over skeys ----
    #pragma unroll
    for (int c = 0; c < PT; c++)
        ((float*)skeys)[pos[c]] = spred[k[c] & 2047u];
    __syncthreads();

    // ---- phase 5: coalesced read of sorted preds, exp, suffix-scan loss ----
    const float4 f0 = ((const float4*)skeys)[2 * tid];
    const float4 f1 = ((const float4*)skeys)[2 * tid + 1];
    float e_[PT];
    e_[0] = __expf(f0.x); e_[1] = __expf(f0.y);
    e_[2] = __expf(f0.z); e_[3] = __expf(f0.w);
    e_[4] = __expf(f1.x); e_[5] = __expf(f1.y);
    e_[6] = __expf(f1.z); e_[7] = __expf(f1.w);

    float T = 0.0f;
    #pragma unroll
    for (int c = 0; c < PT; c++) T += e_[c];

    float xs = T;
    #pragma unroll
    for (int o = 1; o < 32; o <<= 1) {
        const float n = __shfl_up_sync(0xffffffffu, xs, o);
        if (lane >= o) xs += n;
    }
    if (lane == 31) swarp[warp] = xs;
    __syncthreads();
    if (warp == 0) {
        float w = (lane < NW) ? swarp[lane] : 0.0f;
        #pragma unroll
        for (int o = 1; o < NW; o <<= 1) {
            const float n = __shfl_up_sync(0xffffffffu, w, o);
            if (lane >= o) w += n;
        }
        if (lane < NW) swarp[lane] = w;
    }
    __syncthreads();
    const float incl       = xs + (warp > 0 ? swarp[warp - 1] : 0.0f);
    const float total      = swarp[NW - 1];
    const float suffix_off = total - incl;   // sum over positions owned by tid' > tid

    const float EPS = 1e-10f;
    float run  = suffix_off;
    float lsum = 0.0f;
    #pragma unroll
    for (int c = PT - 1; c >= 0; c--) {
        run += e_[c];
        const float P = __fdividef(e_[c], run + EPS);
        lsum += __logf(P + EPS);
    }

    // ---- block reduce of lsum ----
    #pragma unroll
    for (int o = 16; o > 0; o >>= 1)
        lsum += __shfl_down_sync(0xffffffffu, lsum, o);
    __syncthreads();                     // swarp reads above complete
    if (lane == 0) swarp[warp] = lsum;
    __syncthreads();
    if (tid == 0) {
        float s = 0.0f;
        #pragma unroll
        for (int w = 0; w < NW; w++) s += swarp[w];
        g_row_loss[row] = -s;
    }

    // ---- last-CTA final reduction (deterministic value) ----
    __threadfence();
    if (tid == 0)
        isLast = (atomicAdd(&g_counter, 1u) == (unsigned int)(B - 1));
    __syncthreads();
    if (isLast) {
        float v = 0.0f;
        for (int i = tid; i < B; i += NT) v += g_row_loss[i];
        #pragma unroll
        for (int o = 16; o > 0; o >>= 1)
            v += __shfl_down_sync(0xffffffffu, v, o);
        if (lane == 0) swarp[warp] = v;
        __syncthreads();
        if (tid == 0) {
            float s = 0.0f;
            #pragma unroll
            for (int w = 0; w < NW; w++) s += swarp[w];
            out[0] = s / (float)B;
            g_counter = 0u;              // reset for next graph replay
        }
    }
}

extern "C" void kernel_launch(void* const* d_in, const int* in_sizes, int n_in,
                              void* d_out, int out_size) {
    const float* preds = (const float*)d_in[0];
    const float* targs = (const float*)d_in[1];
    const int B = in_sizes[0] / L;
    listmle_fused_kernel<<<B, NT>>>(preds, targs, (float*)d_out);
}

// round 11
// speedup vs baseline: 1.1732x; 1.1732x over previous
#include <cuda_runtime.h>
#include <stdint.h>

#define L 2048
#define NT 256
#define PT 8
#define NW (NT / 32)
#define BMAX 4096

__device__ float g_row_loss[BMAX];

// Map float -> uint such that uint order == float ascending order.
__device__ __forceinline__ unsigned int f2u_ord(float f) {
    unsigned int u = __float_as_uint(f);
    return (u & 0x80000000u) ? ~u : (u | 0x80000000u);
}

// Bucket id (0..2047), an exact monotone-nondecreasing function of the key.
// Reconstruct canonical target from key's top 21 bits, map through a logistic
// CDF (targets ~ N(0,1)) so occupancy is ~Poisson(1).
__device__ __forceinline__ unsigned int bucket_of(unsigned int key) {
    const unsigned int o = (~key) & 0xFFFFF800u;       // truncated ord(t)
    const unsigned int u = (o & 0x80000000u) ? (o ^ 0x80000000u) : ~o;
    const float t = __uint_as_float(u);
    const float p = __fdividef(2048.0f, 1.0f + __expf(1.702f * t));
    int b = (int)p;                                     // decreasing in t
    return (unsigned int)min(b, 2047);
}

__global__ __launch_bounds__(NT)
void listmle_row_kernel(const float* __restrict__ preds,
                        const float* __restrict__ targs) {
    __shared__ unsigned int hist[L];        // 8 KB  counts -> exclusive base
    __shared__ unsigned int skeys[L];       // 8 KB  keys, then sorted preds
    __shared__ unsigned int uwarp[NW];
    __shared__ float swarp[NW];

    const int row  = blockIdx.x;
    const int tid  = threadIdx.x;
    const int lane = tid & 31;
    const int warp = tid >> 5;

    const float4* p4 = (const float4*)(preds + (size_t)row * L);
    const float4* t4 = (const float4*)(targs + (size_t)row * L);

    // ---- phase 0: load preds into REGISTERS; build keys + buckets; zero hist
    // key = top-21 bits of ~ord(target) | 11-bit original index (all distinct)
    float pr[PT];
    unsigned int k[PT], bkt[PT];
    #pragma unroll
    for (int u = 0; u < 2; u++) {
        const float4 pv = p4[u * NT + tid];
        pr[4*u+0] = pv.x; pr[4*u+1] = pv.y; pr[4*u+2] = pv.z; pr[4*u+3] = pv.w;
        const float4 tv = t4[u * NT + tid];
        const unsigned int e = (unsigned int)((u * NT + tid) * 4);
        k[4*u+0] = (~f2u_ord(tv.x) & 0xFFFFF800u) | (e + 0u);
        k[4*u+1] = (~f2u_ord(tv.y) & 0xFFFFF800u) | (e + 1u);
        k[4*u+2] = (~f2u_ord(tv.z) & 0xFFFFF800u) | (e + 2u);
        k[4*u+3] = (~f2u_ord(tv.w) & 0xFFFFF800u) | (e + 3u);
    }
    #pragma unroll
    for (int c = 0; c < PT; c++) bkt[c] = bucket_of(k[c]);
    ((uint4*)hist)[tid]      = make_uint4(0u, 0u, 0u, 0u);
    ((uint4*)hist)[NT + tid] = make_uint4(0u, 0u, 0u, 0u);
    __syncthreads();

    // ---- phase 1: histogram, remember arrival index ----
    unsigned int arr[PT];
    #pragma unroll
    for (int c = 0; c < PT; c++)
        arr[c] = atomicAdd(&hist[bkt[c]], 1u);
    __syncthreads();

    // ---- phase 2: exclusive scan of hist[2048] in place (uint4 I/O) ----
    unsigned int h[PT];
    {
        const uint4 ha = ((const uint4*)hist)[2 * tid];
        const uint4 hb = ((const uint4*)hist)[2 * tid + 1];
        h[0] = ha.x; h[1] = ha.y; h[2] = ha.z; h[3] = ha.w;
        h[4] = hb.x; h[5] = hb.y; h[6] = hb.z; h[7] = hb.w;
    }
    unsigned int tsum = 0u;
    #pragma unroll
    for (int c = 0; c < PT; c++) { const unsigned int t = h[c]; h[c] = tsum; tsum += t; }
    unsigned int x = tsum;
    #pragma unroll
    for (int o = 1; o < 32; o <<= 1) {
        const unsigned int n = __shfl_up_sync(0xffffffffu, x, o);
        if (lane >= o) x += n;
    }
    if (lane == 31) uwarp[warp] = x;
    __syncthreads();
    if (warp == 0) {
        unsigned int w = (lane < NW) ? uwarp[lane] : 0u;
        #pragma unroll
        for (int o = 1; o < NW; o <<= 1) {
            const unsigned int n = __shfl_up_sync(0xffffffffu, w, o);
            if (lane >= o) w += n;
        }
        if (lane < NW) uwarp[lane] = w;
    }
    __syncthreads();
    const unsigned int excl = (x - tsum) + (warp > 0 ? uwarp[warp - 1] : 0u);
    ((uint4*)hist)[2 * tid]     = make_uint4(h[0] + excl, h[1] + excl, h[2] + excl, h[3] + excl);
    ((uint4*)hist)[2 * tid + 1] = make_uint4(h[4] + excl, h[5] + excl, h[6] + excl, h[7] + excl);
    __syncthreads();

    // ---- phase 3: scatter keys; keep bucket base in registers ----
    unsigned int base[PT];
    #pragma unroll
    for (int c = 0; c < PT; c++) {
        base[c] = hist[bkt[c]];
        skeys[base[c] + arr[c]] = k[c];
    }
    __syncthreads();

    // ---- phase 4a: exact in-bucket rank (full-key compare) -> registers ----
    unsigned int pos[PT];
    #pragma unroll
    for (int c = 0; c < PT; c++) {
        const unsigned int key  = k[c];
        const unsigned int d    = bkt[c];
        const unsigned int b    = base[c];
        const unsigned int bend = (d < 2047u) ? hist[d + 1] : (unsigned int)L;
        unsigned int r = 0u;
        for (unsigned int p = b; p < bend; p++)
            r += (skeys[p] < key) ? 1u : 0u;
        pos[c] = b + r;
    }
    __syncthreads();

    // ---- phase 4b: write sorted pred values (from registers) over skeys ----
    #pragma unroll
    for (int c = 0; c < PT; c++)
        ((float*)skeys)[pos[c]] = pr[c];
    __syncthreads();

    // ---- phase 5: coalesced read of sorted preds, exp, suffix-scan loss ----
    const float4 f0 = ((const float4*)skeys)[2 * tid];
    const float4 f1 = ((const float4*)skeys)[2 * tid + 1];
    float e_[PT];
    e_[0] = __expf(f0.x); e_[1] = __expf(f0.y);
    e_[2] = __expf(f0.z); e_[3] = __expf(f0.w);
    e_[4] = __expf(f1.x); e_[5] = __expf(f1.y);
    e_[6] = __expf(f1.z); e_[7] = __expf(f1.w);

    float T = 0.0f;
    #pragma unroll
    for (int c = 0; c < PT; c++) T += e_[c];

    float xs = T;
    #pragma unroll
    for (int o = 1; o < 32; o <<= 1) {
        const float n = __shfl_up_sync(0xffffffffu, xs, o);
        if (lane >= o) xs += n;
    }
    if (lane == 31) swarp[warp] = xs;
    __syncthreads();
    if (warp == 0) {
        float w = (lane < NW) ? swarp[lane] : 0.0f;
        #pragma unroll
        for (int o = 1; o < NW; o <<= 1) {
            const float n = __shfl_up_sync(0xffffffffu, w, o);
            if (lane >= o) w += n;
        }
        if (lane < NW) swarp[lane] = w;
    }
    __syncthreads();
    const float incl       = xs + (warp > 0 ? swarp[warp - 1] : 0.0f);
    const float total      = swarp[NW - 1];
    const float suffix_off = total - incl;   // sum over positions owned by tid' > tid

    const float EPS = 1e-10f;
    float run  = suffix_off;
    float lsum = 0.0f;
    #pragma unroll
    for (int c = PT - 1; c >= 0; c--) {
        run += e_[c];
        const float P = __fdividef(e_[c], run + EPS);
        lsum += __logf(P + EPS);
    }

    // ---- block reduce of lsum ----
    #pragma unroll
    for (int o = 16; o > 0; o >>= 1)
        lsum += __shfl_down_sync(0xffffffffu, lsum, o);
    __syncthreads();                     // swarp reads above complete
    if (lane == 0) swarp[warp] = lsum;
    __syncthreads();
    if (tid == 0) {
        float s = 0.0f;
        #pragma unroll
        for (int w = 0; w < NW; w++) s += swarp[w];
        g_row_loss[row] = -s;
    }
}

__global__ __launch_bounds__(1024)
void listmle_reduce_kernel(float* __restrict__ out, int B) {
    __shared__ float s[32];
    const int tid  = threadIdx.x;
    const int lane = tid & 31;
    const int warp = tid >> 5;
    float v = 0.0f;
    for (int i = tid; i < B; i += 1024) v += g_row_loss[i];
    #pragma unroll
    for (int o = 16; o > 0; o >>= 1)
        v += __shfl_down_sync(0xffffffffu, v, o);
    if (lane == 0) s[warp] = v;
    __syncthreads();
    if (warp == 0) {
        float w = s[lane];
        #pragma unroll
        for (int o = 16; o > 0; o >>= 1)
            w += __shfl_down_sync(0xffffffffu, w, o);
        if (lane == 0) out[0] = w / (float)B;
    }
}

extern "C" void kernel_launch(void* const* d_in, const int* in_sizes, int n_in,
                              void* d_out, int out_size) {
    const float* preds = (const float*)d_in[0];
    const float* targs = (const float*)d_in[1];
    const int B = in_sizes[0] / L;
    listmle_row_kernel<<<B, NT>>>(preds, targs);
    listmle_reduce_kernel<<<1, 1024>>>((float*)d_out, B);
}